// round 6
// baseline (speedup 1.0000x reference)
#include <cuda_runtime.h>
#include <cuda_fp16.h>

#define D 64
#define NMAX 100000
#define EMAX 1000000
#define XPAD 65

// Scratch (allocation-free rule: __device__ globals; zero-init at load,
// k_zero restores counters at end of every call -> deterministic)
__device__ int     g_cnt_out[NMAX];
__device__ int     g_cnt_in[NMAX];
__device__ float   g_isq_out[NMAX];
__device__ float   g_isq_in[NMAX];
__device__ int     g_row_off[NMAX + 1];
__device__ int     g_fill[NMAX];
__device__ int     g_csr_src[EMAX];
__device__ __half2 g_xh[(size_t)NMAX * 32];   // x * isq_out, fp16
__device__ __half2 g_h1h[(size_t)NMAX * 32];  // h1 * isq_out, fp16
__device__ int     g_part[1024];              // block partial sums for scan

// ---------------------------------------------------------------------------
// packed f32x2 helpers (Blackwell FFMA2 — only reachable via PTX)
// ---------------------------------------------------------------------------
__device__ __forceinline__ unsigned long long pack2(float lo, float hi) {
    unsigned long long r;
    asm("mov.b64 %0, {%1, %2};" : "=l"(r) : "f"(lo), "f"(hi));
    return r;
}
__device__ __forceinline__ void unpack2(unsigned long long v, float& lo, float& hi) {
    asm("mov.b64 {%0, %1}, %2;" : "=f"(lo), "=f"(hi) : "l"(v));
}
__device__ __forceinline__ unsigned long long fma2(unsigned long long a,
                                                   unsigned long long b,
                                                   unsigned long long c) {
    unsigned long long d;
    asm("fma.rn.f32x2 %0, %1, %2, %3;" : "=l"(d) : "l"(a), "l"(b), "l"(c));
    return d;
}

// ---------------------------------------------------------------------------
// Degree counting (counters pre-zeroed: module init or trailing k_zero)
// ---------------------------------------------------------------------------
__global__ void k_deg(const int* __restrict__ src, const int* __restrict__ dst, int E) {
    int e = blockIdx.x * blockDim.x + threadIdx.x;
    if (e < E) {
        atomicAdd(&g_cnt_out[src[e]], 1);
        atomicAdd(&g_cnt_in[dst[e]], 1);
    }
}

// scan step 1: per-block sums of in-degree
__global__ void k_scan1(int N) {
    __shared__ int s[256];
    int t = threadIdx.x;
    int n = blockIdx.x * 256 + t;
    s[t] = (n < N) ? g_cnt_in[n] : 0;
    __syncthreads();
#pragma unroll
    for (int off = 128; off > 0; off >>= 1) {
        if (t < off) s[t] += s[t + off];
        __syncthreads();
    }
    if (t == 0) g_part[blockIdx.x] = s[0];
}

// scan step 2: exclusive scan of up to 512 block sums (single block)
__global__ void k_scan2(int NB) {
    __shared__ int s[512];
    int t = threadIdx.x;
    s[t] = (t < NB) ? g_part[t] : 0;
    __syncthreads();
    for (int off = 1; off < 512; off <<= 1) {
        int v = (t >= off) ? s[t - off] : 0;
        __syncthreads();
        s[t] += v;
        __syncthreads();
    }
    if (t < NB) g_part[t] = (t == 0) ? 0 : s[t - 1];
}

// scan step 3: row offsets, fill=0, isqrt degrees
__global__ void k_scan3(int N, int E) {
    __shared__ int s[256];
    int t = threadIdx.x;
    int n = blockIdx.x * 256 + t;
    int c = (n < N) ? g_cnt_in[n] : 0;
    s[t] = c;
    __syncthreads();
    for (int off = 1; off < 256; off <<= 1) {
        int v = (t >= off) ? s[t - off] : 0;
        __syncthreads();
        s[t] += v;
        __syncthreads();
    }
    if (n < N) {
        int excl = s[t] - c + g_part[blockIdx.x];
        g_row_off[n] = excl;
        g_fill[n] = 0;
        g_isq_in[n]  = rsqrtf((float)max(c, 1));
        g_isq_out[n] = rsqrtf((float)max(g_cnt_out[n], 1));
    }
    if (n == 0) g_row_off[N] = E;
}

// place edges (csr_src grouped by dst) + prep fp16 scaled features
__global__ void k_place_prep(const int* __restrict__ src, const int* __restrict__ dst,
                             const float* __restrict__ x, int E, int N) {
    int i = blockIdx.x * blockDim.x + threadIdx.x;
    if (i < E) {
        int d = dst[i];
        int pos = g_row_off[d] + atomicAdd(&g_fill[d], 1);
        g_csr_src[pos] = src[i];
    }
    int total = N * 32;
    int stride = gridDim.x * blockDim.x;
    for (int j = i; j < total; j += stride) {
        int n = j >> 5, c = j & 31;
        float iso = g_isq_out[n];
        float2 v = reinterpret_cast<const float2*>(x)[(size_t)n * 32 + c];
        g_xh[(size_t)n * 32 + c] = __floats2half2_rn(v.x * iso, v.y * iso);
    }
}

// trailing cleanup so the next call starts from zeroed counters
__global__ void k_zero(int N) {
    int i = blockIdx.x * blockDim.x + threadIdx.x;
    if (i < N) { g_cnt_out[i] = 0; g_cnt_in[i] = 0; }
}

// ---------------------------------------------------------------------------
// Fused aggregate + GEMM (+ optional classifier).
// 256 threads, 128 nodes/block.
// Phase 1: warp w owns 16 nodes; lane l sums cols 2l,2l+1 of fp16 pre-scaled
//   source rows (isq_out folded in), then * isq_in[n], into smem X tile.
// Phase 2: warp -> col quarter q=w&3 (W loads warp-uniform broadcast);
//   thread = 2 adjacent nodes x 16 cols, packed f32x2 FMAs.
// FUSE=false: writes h1 * isq_out as half2. FUSE=true: 64->2 classifier.
// ---------------------------------------------------------------------------
template <bool FUSE>
__global__ __launch_bounds__(256, 3) void k_fused(
        const __half2* __restrict__ xin,
        const float* __restrict__ W,
        const float* __restrict__ b,
        const float* __restrict__ Wc,
        const float* __restrict__ bc,
        __half2* __restrict__ out_h,
        float* __restrict__ out_f, int N) {
    extern __shared__ float smem[];
    float* sW   = smem;                     // 4096
    float* sX   = sW + D * D;               // 128 * XPAD
    float* sCls = sX + 128 * XPAD;          // 128 * 8
    float* sWc  = sCls + 128 * 8;           // 128

    int tid = threadIdx.x;
    int w = tid >> 5;
    int lane = tid & 31;
    int nb = blockIdx.x * 128;

    for (int i = tid; i < D * D; i += 256) sW[i] = W[i];
    if (FUSE && tid < D * 2) sWc[tid] = Wc[tid];

    // ---- Phase 1: aggregation into sX (fp16 payload, fp32 accumulate) ----
    const int* __restrict__ csr = g_csr_src;
#pragma unroll 1
    for (int nn = 0; nn < 16; nn++) {
        int local = w * 16 + nn;
        int n = nb + local;
        float ax = 0.0f, ay = 0.0f;
        if (n < N) {
            int beg = g_row_off[n];
            int end = g_row_off[n + 1];
            int e = beg;
            for (; e + 7 < end; e += 8) {
                int s0 = csr[e],     s1 = csr[e + 1], s2 = csr[e + 2], s3 = csr[e + 3];
                int s4 = csr[e + 4], s5 = csr[e + 5], s6 = csr[e + 6], s7 = csr[e + 7];
                float2 f0 = __half22float2(xin[(size_t)s0 * 32 + lane]);
                float2 f1 = __half22float2(xin[(size_t)s1 * 32 + lane]);
                float2 f2 = __half22float2(xin[(size_t)s2 * 32 + lane]);
                float2 f3 = __half22float2(xin[(size_t)s3 * 32 + lane]);
                float2 f4 = __half22float2(xin[(size_t)s4 * 32 + lane]);
                float2 f5 = __half22float2(xin[(size_t)s5 * 32 + lane]);
                float2 f6 = __half22float2(xin[(size_t)s6 * 32 + lane]);
                float2 f7 = __half22float2(xin[(size_t)s7 * 32 + lane]);
                ax += (f0.x + f1.x) + (f2.x + f3.x) + (f4.x + f5.x) + (f6.x + f7.x);
                ay += (f0.y + f1.y) + (f2.y + f3.y) + (f4.y + f5.y) + (f6.y + f7.y);
            }
            for (; e < end; e++) {
                float2 f0 = __half22float2(xin[(size_t)csr[e] * 32 + lane]);
                ax += f0.x; ay += f0.y;
            }
            float si = g_isq_in[n];
            ax *= si; ay *= si;
        }
        sX[local * XPAD + 2 * lane]     = ax;
        sX[local * XPAD + 2 * lane + 1] = ay;
    }
    __syncthreads();

    // ---- Phase 2: GEMM ----
    int q = w & 3;                 // column quarter (warp-uniform)
    int half = w >> 2;             // node half
    int n0 = half * 64 + 2 * lane; // local node (even); thread does n0, n0+1

    unsigned long long acc[2][8];
    {
        unsigned long long binit[8];
#pragma unroll
        for (int j = 0; j < 8; j++)
            binit[j] = pack2(b[q * 16 + 2 * j], b[q * 16 + 2 * j + 1]);
#pragma unroll
        for (int j = 0; j < 8; j++) { acc[0][j] = binit[j]; acc[1][j] = binit[j]; }
    }

    unsigned wbase = (unsigned)__cvta_generic_to_shared(&sW[q * 16]);
    unsigned xbase0 = (unsigned)__cvta_generic_to_shared(&sX[n0 * XPAD]);
    unsigned xbase1 = xbase0 + XPAD * 4;

#pragma unroll 8
    for (int k = 0; k < D; k++) {
        unsigned long long w2[8];
        unsigned waddr = wbase + k * (D * 4);
        asm("ld.shared.v2.u64 {%0,%1}, [%2];" : "=l"(w2[0]), "=l"(w2[1]) : "r"(waddr));
        asm("ld.shared.v2.u64 {%0,%1}, [%2];" : "=l"(w2[2]), "=l"(w2[3]) : "r"(waddr + 16));
        asm("ld.shared.v2.u64 {%0,%1}, [%2];" : "=l"(w2[4]), "=l"(w2[5]) : "r"(waddr + 32));
        asm("ld.shared.v2.u64 {%0,%1}, [%2];" : "=l"(w2[6]), "=l"(w2[7]) : "r"(waddr + 48));
        float a0, a1;
        asm("ld.shared.f32 %0, [%1];" : "=f"(a0) : "r"(xbase0 + k * 4));
        asm("ld.shared.f32 %0, [%1];" : "=f"(a1) : "r"(xbase1 + k * 4));
        unsigned long long a0p = pack2(a0, a0);
        unsigned long long a1p = pack2(a1, a1);
#pragma unroll
        for (int j = 0; j < 8; j++) {
            acc[0][j] = fma2(a0p, w2[j], acc[0][j]);
            acc[1][j] = fma2(a1p, w2[j], acc[1][j]);
        }
    }

#pragma unroll
    for (int m = 0; m < 2; m++) {
        int local = n0 + m;
        int node = nb + local;
        float v[16];
#pragma unroll
        for (int j = 0; j < 8; j++) unpack2(acc[m][j], v[2 * j], v[2 * j + 1]);
#pragma unroll
        for (int j = 0; j < 16; j++) v[j] = v[j] > 0.0f ? v[j] : 0.01f * v[j];

        if (!FUSE) {
            if (node < N) {
                float so = g_isq_out[node];       // fold next layer's source scale
                unsigned hp[8];
#pragma unroll
                for (int j = 0; j < 8; j++) {
                    __half2 h = __floats2half2_rn(v[2 * j] * so, v[2 * j + 1] * so);
                    hp[j] = *reinterpret_cast<unsigned*>(&h);
                }
                uint4* o = reinterpret_cast<uint4*>(out_h + (size_t)node * 32 + q * 8);
                o[0] = make_uint4(hp[0], hp[1], hp[2], hp[3]);
                o[1] = make_uint4(hp[4], hp[5], hp[6], hp[7]);
            }
        } else {
            float p0 = 0.0f, p1 = 0.0f;
#pragma unroll
            for (int j = 0; j < 16; j++) {
                int f = q * 16 + j;
                p0 = fmaf(v[j], sWc[2 * f + 0], p0);
                p1 = fmaf(v[j], sWc[2 * f + 1], p1);
            }
            sCls[local * 8 + q * 2 + 0] = p0;
            sCls[local * 8 + q * 2 + 1] = p1;
        }
    }

    if (FUSE) {
        __syncthreads();
        int local = tid >> 1;
        int o = tid & 1;
        int node = nb + local;
        if (node < N) {
            float p = sCls[local * 8 + 0 * 2 + o] + sCls[local * 8 + 1 * 2 + o]
                    + sCls[local * 8 + 2 * 2 + o] + sCls[local * 8 + 3 * 2 + o];
            out_f[(size_t)node * 2 + o] = p + bc[o];
        }
    }
}

// ---------------------------------------------------------------------------
extern "C" void kernel_launch(void* const* d_in, const int* in_sizes, int n_in,
                              void* d_out, int out_size) {
    const float* x  = (const float*)d_in[0];
    const int*   src = (const int*)d_in[1];
    const int*   dst = (const int*)d_in[2];
    const float* W1 = (const float*)d_in[3];
    const float* b1 = (const float*)d_in[4];
    const float* W2 = (const float*)d_in[5];
    const float* b2 = (const float*)d_in[6];
    const float* Wc = (const float*)d_in[7];
    const float* bc = (const float*)d_in[8];
    float* out = (float*)d_out;

    int N = in_sizes[0] / D;
    int E = in_sizes[1];

    void *p_xh, *p_h1h;
    cudaGetSymbolAddress(&p_xh,  g_xh);
    cudaGetSymbolAddress(&p_h1h, g_h1h);

    size_t smem_bytes = (D * D + 128 * XPAD + 128 * 8 + 128) * sizeof(float);
    static bool attr_set = false;
    if (!attr_set) {
        cudaFuncSetAttribute(k_fused<false>, cudaFuncAttributeMaxDynamicSharedMemorySize,
                             (int)smem_bytes);
        cudaFuncSetAttribute(k_fused<true>, cudaFuncAttributeMaxDynamicSharedMemorySize,
                             (int)smem_bytes);
        attr_set = true;
    }

    int NB = (N + 255) / 256;   // scan blocks (<= 512)
    int gblk = (N + 127) / 128;

    // CSR build + degree scales (counters zeroed by module init / trailing k_zero)
    k_deg<<<(E + 255) / 256, 256>>>(src, dst, E);
    k_scan1<<<NB, 256>>>(N);
    k_scan2<<<1, 512>>>(NB);
    k_scan3<<<NB, 256>>>(N, E);
    k_place_prep<<<(E + 255) / 256, 256>>>(src, dst, x, E, N);

    // layer 1: xh -> h1h (fp16, isq_out pre-folded)
    k_fused<false><<<gblk, 256, smem_bytes>>>((const __half2*)p_xh, W1, b1,
                                              nullptr, nullptr,
                                              (__half2*)p_h1h, nullptr, N);
    // layer 2 + classifier: h1h -> out
    k_fused<true><<<gblk, 256, smem_bytes>>>((const __half2*)p_h1h, W2, b2, Wc, bc,
                                             nullptr, out, N);

    // reset counters for next call
    k_zero<<<(N + 255) / 256, 256>>>(N);
}